// round 9
// baseline (speedup 1.0000x reference)
#include <cuda_runtime.h>
#include <cuda_bf16.h>
#include <cuda_fp16.h>
#include <cuda_fp8.h>
#include <cstdint>
#include <cstddef>

#define MDIM 8192
#define KDIM 4096
#define NDIM 4096
#define BM 128
#define BN 128
#define BK 32
#define STAGES 4
#define KITERS (KDIM / BK)          // 128
#define NKB (KDIM / 128)            // 32 k-blocks
#define THREADS 512

// Padded smem row: 32 halves data + 8 halves pad = 40 halves = 80 B (conflict-free ldmatrix)
#define ROW_HALVES 40
#define TILE_BYTES (128 * ROW_HALVES * 2)     // 10240
#define STAGE_BYTES (2 * TILE_BYTES)          // A + B = 20480
#define SMEM_TOTAL (STAGES * STAGE_BYTES)     // 81920

// ---- scratch (static device arrays; no allocation) ----
__device__ __half g_A[(size_t)MDIM * KDIM];    // raw fp8 grid values of x/s, exact in fp16
__device__ __half g_W[(size_t)NDIM * KDIM];    // raw fp8 grid values of w, exact in fp16
__device__ float  g_SA[(size_t)MDIM * NKB];    // activation scales [M][32]

// ------------------------------ PTX helpers ------------------------------
__device__ __forceinline__ uint32_t smem_u32(const void* p) {
    uint32_t a;
    asm("{ .reg .u64 t; cvta.to.shared.u64 t, %1; cvt.u32.u64 %0, t; }" : "=r"(a) : "l"(p));
    return a;
}
__device__ __forceinline__ void cp16(uint32_t dst, const void* src) {
    asm volatile("cp.async.cg.shared.global [%0], [%1], 16;" :: "r"(dst), "l"(src) : "memory");
}
__device__ __forceinline__ void cp_commit() {
    asm volatile("cp.async.commit_group;" ::: "memory");
}
template <int N>
__device__ __forceinline__ void cp_wait() {
    asm volatile("cp.async.wait_group %0;" :: "n"(N) : "memory");
}
__device__ __forceinline__ void ldsm_x4(uint32_t* r, uint32_t addr) {
    asm volatile("ldmatrix.sync.aligned.m8n8.x4.shared.b16 {%0,%1,%2,%3}, [%4];"
                 : "=r"(r[0]), "=r"(r[1]), "=r"(r[2]), "=r"(r[3]) : "r"(addr));
}
__device__ __forceinline__ void mma16816(float* c, const uint32_t* a, uint32_t b0, uint32_t b1) {
    asm volatile(
        "mma.sync.aligned.m16n8k16.row.col.f32.f16.f16.f32 "
        "{%0,%1,%2,%3}, {%4,%5,%6,%7}, {%8,%9}, {%0,%1,%2,%3};"
        : "+f"(c[0]), "+f"(c[1]), "+f"(c[2]), "+f"(c[3])
        : "r"(a[0]), "r"(a[1]), "r"(a[2]), "r"(a[3]), "r"(b0), "r"(b1));
}

// fp8 e4m3 quantize, return the exact fp8 grid value as fp16 (no scale baked in)
__device__ __forceinline__ __half fp8_q(float v) {
    __nv_fp8_storage_t q = __nv_cvt_float_to_fp8(v, __NV_SATFINITE, __NV_E4M3);
    __half_raw hr = __nv_cvt_fp8_to_halfraw(q, __NV_E4M3);
    return __half(hr);
}

// ------------------------------ quantize kernels ------------------------------
// One warp per (row, 128-block): amax -> scale -> q values (exact fp16) + scale to g_SA
__global__ void __launch_bounds__(256) quant_x_kernel(const float* __restrict__ x) {
    const int gw   = (blockIdx.x * 256 + threadIdx.x) >> 5;
    const int lane = threadIdx.x & 31;
    const int m  = gw >> 5;
    const int kb = gw & 31;
    const size_t base = (size_t)m * KDIM + kb * 128 + lane * 4;
    const float4 v = *reinterpret_cast<const float4*>(x + base);
    float amax = fmaxf(fmaxf(fabsf(v.x), fabsf(v.y)), fmaxf(fabsf(v.z), fabsf(v.w)));
#pragma unroll
    for (int o = 16; o > 0; o >>= 1)
        amax = fmaxf(amax, __shfl_xor_sync(0xFFFFFFFFu, amax, o));
    const float s = fmaxf(amax, 1e-12f) / 448.0f;
    __half h[4];
    h[0] = fp8_q(v.x / s);
    h[1] = fp8_q(v.y / s);
    h[2] = fp8_q(v.z / s);
    h[3] = fp8_q(v.w / s);
    *reinterpret_cast<uint2*>(g_A + base) = *reinterpret_cast<uint2*>(h);
    if (lane == 0) g_SA[(size_t)m * NKB + kb] = s;
}

__global__ void __launch_bounds__(256) quant_w_kernel(const float* __restrict__ w) {
    const size_t e = ((size_t)blockIdx.x * 256 + threadIdx.x) * 4;
    const float4 v = *reinterpret_cast<const float4*>(w + e);
    __half h[4];
    h[0] = fp8_q(v.x);
    h[1] = fp8_q(v.y);
    h[2] = fp8_q(v.z);
    h[3] = fp8_q(v.w);
    *reinterpret_cast<uint2*>(g_W + e) = *reinterpret_cast<uint2*>(h);
}

// ------------------------------ GEMM kernel ------------------------------
// 128x128x32 CTA tile, 16 warps (4m x 4n), warp tile 32x32, mma.sync m16n8k16.
// Two-level accumulation: raw q products in temp (fp32), promoted to master with
// fp32 block scales every 128-k block (exact block-scaled fp8 GEMM).
__global__ void __launch_bounds__(THREADS, 1) gemm_kernel(const float* __restrict__ wsi,
                                                          const float* __restrict__ bias,
                                                          float* __restrict__ out) {
    extern __shared__ __align__(128) char smem[];
    const uint32_t sb = smem_u32(smem);
    const int tid  = threadIdx.x;
    const int lane = tid & 31;
    const int wid  = tid >> 5;
    const int wm   = wid & 3;       // 4 warps along M
    const int wn   = wid >> 2;      // 4 warps along N
    const int m0 = blockIdx.y * BM;
    const int n0 = blockIdx.x * BN;
    const float* wsi_cta = wsi + blockIdx.x * NKB;   // s_w per k-block for this n-block

    float master[2][4][4];
    float temp[2][4][4];
#pragma unroll
    for (int i = 0; i < 2; ++i)
#pragma unroll
        for (int j = 0; j < 4; ++j)
#pragma unroll
            for (int q = 0; q < 4; ++q) { master[i][j][q] = 0.0f; temp[i][j][q] = 0.0f; }

    // producer: 1024 16B chunks per stage, 2 per thread
    auto load_stage = [&](int k, int s) {
        const int k0 = k * BK;
        const uint32_t base = sb + s * STAGE_BYTES;
#pragma unroll
        for (int i = 0; i < 2; ++i) {
            const int cid  = tid + (i << 9);
            const int tile = cid >> 9;          // 0 = A, 1 = B
            const int w    = cid & 511;
            const int r    = w >> 2;
            const int ch   = w & 3;
            const __half* src = (tile == 0)
                ? g_A + (size_t)(m0 + r) * KDIM + k0 + (ch << 3)
                : g_W + (size_t)(n0 + r) * KDIM + k0 + (ch << 3);
            const uint32_t dst = base + tile * TILE_BYTES
                + (uint32_t)(r * ROW_HALVES + (ch << 3)) * 2;
            cp16(dst, src);
        }
    };

#pragma unroll
    for (int s = 0; s < STAGES - 1; ++s) { load_stage(s, s); cp_commit(); }

    const int arow0 = m0 + wm * 32 + (lane >> 2);    // this thread's scale rows

    for (int k = 0; k < KITERS; ++k) {
        cp_wait<STAGES - 2>();
        __syncthreads();

        const int s = k & (STAGES - 1);
        const uint32_t aBase = sb + s * STAGE_BYTES;
        const uint32_t bBase = aBase + TILE_BYTES;
#pragma unroll
        for (int kk = 0; kk < 2; ++kk) {
            uint32_t a[2][4];
#pragma unroll
            for (int mi = 0; mi < 2; ++mi) {
                const int row = wm * 32 + mi * 16 + (lane & 15);
                const int col = kk * 16 + ((lane >> 4) << 3);
                ldsm_x4(a[mi], aBase + (uint32_t)(row * ROW_HALVES + col) * 2);
            }
            uint32_t b[2][4];   // non-trans x4 on [n][k]: r0=(nlo,klo) r1=(nhi,klo) r2=(nlo,khi) r3=(nhi,khi)
#pragma unroll
            for (int nj = 0; nj < 2; ++nj) {
                const int row = wn * 32 + nj * 16 + (((lane >> 3) & 1) << 3) + (lane & 7);
                const int col = kk * 16 + ((lane >> 4) << 3);
                ldsm_x4(b[nj], bBase + (uint32_t)(row * ROW_HALVES + col) * 2);
            }
#pragma unroll
            for (int mi = 0; mi < 2; ++mi)
#pragma unroll
                for (int ni = 0; ni < 4; ++ni)
                    mma16816(temp[mi][ni], a[mi], b[ni >> 1][ni & 1], b[ni >> 1][2 + (ni & 1)]);
        }

        const int kn = k + STAGES - 1;
        if (kn < KITERS) load_stage(kn, kn & (STAGES - 1));
        cp_commit();

        if ((k & 3) == 3) {
            // promote: master += s_w(kb) * s_a(row,kb) * temp ; temp = 0
            const int kb = k >> 2;
            const float sw = __ldg(wsi_cta + kb);
            float comb[2][2];
#pragma unroll
            for (int mi = 0; mi < 2; ++mi)
#pragma unroll
                for (int h = 0; h < 2; ++h)
                    comb[mi][h] = sw * __ldg(g_SA + (size_t)(arow0 + mi * 16 + h * 8) * NKB + kb);
#pragma unroll
            for (int mi = 0; mi < 2; ++mi)
#pragma unroll
                for (int ni = 0; ni < 4; ++ni)
#pragma unroll
                    for (int q = 0; q < 4; ++q) {
                        master[mi][ni][q] = fmaf(comb[mi][q >> 1], temp[mi][ni][q], master[mi][ni][q]);
                        temp[mi][ni][q] = 0.0f;
                    }
        }
    }

    // -------- epilogue: bf16 arithmetic (match reference), write FLOAT32 --------
    // c[mi][ni][q]: row = wm*32+mi*16+(lane>>2)+(q>>1)*8, col = wn*32+ni*8+(lane&3)*2+(q&1)
#pragma unroll
    for (int mi = 0; mi < 2; ++mi)
#pragma unroll
        for (int h = 0; h < 2; ++h) {
            const int grow = m0 + wm * 32 + mi * 16 + (lane >> 2) + h * 8;
            float* orow = out + (size_t)grow * NDIM;
#pragma unroll
            for (int ni = 0; ni < 4; ++ni) {
                const int col = n0 + wn * 32 + ni * 8 + ((lane & 3) << 1);
                const float b0 = __bfloat162float(__float2bfloat16(bias[col]));
                const float b1 = __bfloat162float(__float2bfloat16(bias[col + 1]));
                const float v0 = __bfloat162float(__float2bfloat16(master[mi][ni][h * 2 + 0]));
                const float v1 = __bfloat162float(__float2bfloat16(master[mi][ni][h * 2 + 1]));
                float2 o;
                o.x = __bfloat162float(__float2bfloat16(v0 + b0));
                o.y = __bfloat162float(__float2bfloat16(v1 + b1));
                *reinterpret_cast<float2*>(orow + col) = o;
            }
        }
}

// ------------------------------ launch ------------------------------
extern "C" void kernel_launch(void* const* d_in, const int* in_sizes, int n_in,
                              void* d_out, int out_size) {
    (void)out_size;
    // Bind inputs BY ELEMENT COUNT (robust to metadata ordering):
    //   x: 33554432, w: 16777216, wsi: 1024, bias: 4096
    const float* x    = nullptr;
    const float* w    = nullptr;
    const float* wsi  = nullptr;
    const float* bias = nullptr;
    for (int i = 0; i < n_in; ++i) {
        switch (in_sizes[i]) {
            case 33554432: x    = (const float*)d_in[i]; break;
            case 16777216: w    = (const float*)d_in[i]; break;
            case 1024:     wsi  = (const float*)d_in[i]; break;
            case 4096:     bias = (const float*)d_in[i]; break;
            default: break;
        }
    }
    float* out = (float*)d_out;     // __output__ is float32

    quant_x_kernel<<<MDIM * 4, 256>>>(x);
    quant_w_kernel<<<(NDIM * KDIM) / 1024, 256>>>(w);

    cudaFuncSetAttribute(gemm_kernel, cudaFuncAttributeMaxDynamicSharedMemorySize, SMEM_TOTAL);
    dim3 grid(NDIM / BN, MDIM / BM);                // (32, 64)
    gemm_kernel<<<grid, THREADS, SMEM_TOTAL>>>(wsi, bias, out);
}

// round 11
// speedup vs baseline: 1.0224x; 1.0224x over previous
#include <cuda_runtime.h>
#include <cuda_bf16.h>
#include <cuda_fp16.h>
#include <cuda_fp8.h>
#include <cstdint>
#include <cstddef>

#define MDIM 8192
#define KDIM 4096
#define NDIM 4096
#define BM 128
#define BN 128
#define BK 64
#define STAGES 4
#define KITERS (KDIM / BK)          // 64
#define NKB (KDIM / 128)            // 32 k-blocks
#define THREADS 512

// fp8 tile row: 64 B data + 16 B pad = 80 B stride.
// 8 consecutive rows -> byte offsets mod 128 = {0,80,32,112,64,16,96,48}: conflict-free ldmatrix.
#define ROW_BYTES 80
#define TILE_BYTES (128 * ROW_BYTES)          // 10240
#define STAGE_BYTES (2 * TILE_BYTES)          // A + B = 20480
#define SMEM_TOTAL (STAGES * STAGE_BYTES)     // 81920

// ---- scratch (static device arrays; no allocation) ----
__device__ uint8_t g_A[(size_t)MDIM * KDIM];   // raw e4m3 bytes of quantized x
__device__ uint8_t g_W[(size_t)NDIM * KDIM];   // raw e4m3 bytes of w
__device__ float   g_SA[(size_t)MDIM * NKB];   // activation scales [M][32]

// ------------------------------ PTX helpers ------------------------------
__device__ __forceinline__ uint32_t smem_u32(const void* p) {
    uint32_t a;
    asm("{ .reg .u64 t; cvta.to.shared.u64 t, %1; cvt.u32.u64 %0, t; }" : "=r"(a) : "l"(p));
    return a;
}
__device__ __forceinline__ void cp16(uint32_t dst, const void* src) {
    asm volatile("cp.async.cg.shared.global [%0], [%1], 16;" :: "r"(dst), "l"(src) : "memory");
}
__device__ __forceinline__ void cp_commit() {
    asm volatile("cp.async.commit_group;" ::: "memory");
}
template <int N>
__device__ __forceinline__ void cp_wait() {
    asm volatile("cp.async.wait_group %0;" :: "n"(N) : "memory");
}
__device__ __forceinline__ void ldsm_x4(uint32_t* r, uint32_t addr) {
    asm volatile("ldmatrix.sync.aligned.m8n8.x4.shared.b16 {%0,%1,%2,%3}, [%4];"
                 : "=r"(r[0]), "=r"(r[1]), "=r"(r[2]), "=r"(r[3]) : "r"(addr));
}
// fp8 e4m3 MMA, k32: same fragment wiring as f16 m16n8k16 with 2-fp8 "b16 units"
__device__ __forceinline__ void mma_fp8(float* c, const uint32_t* a, uint32_t b0, uint32_t b1) {
    asm volatile(
        "mma.sync.aligned.m16n8k32.row.col.f32.e4m3.e4m3.f32 "
        "{%0,%1,%2,%3}, {%4,%5,%6,%7}, {%8,%9}, {%0,%1,%2,%3};"
        : "+f"(c[0]), "+f"(c[1]), "+f"(c[2]), "+f"(c[3])
        : "r"(a[0]), "r"(a[1]), "r"(a[2]), "r"(a[3]), "r"(b0), "r"(b1));
}

__device__ __forceinline__ uint8_t fp8_q(float v) {
    return (uint8_t)__nv_cvt_float_to_fp8(v, __NV_SATFINITE, __NV_E4M3);
}

// ------------------------------ quantize kernels ------------------------------
// One warp per (row, 128-block): amax -> scale -> raw e4m3 bytes + scale to g_SA
__global__ void __launch_bounds__(256) quant_x_kernel(const float* __restrict__ x) {
    const int gw   = (blockIdx.x * 256 + threadIdx.x) >> 5;
    const int lane = threadIdx.x & 31;
    const int m  = gw >> 5;
    const int kb = gw & 31;
    const size_t base = (size_t)m * KDIM + kb * 128 + lane * 4;
    const float4 v = *reinterpret_cast<const float4*>(x + base);
    float amax = fmaxf(fmaxf(fabsf(v.x), fabsf(v.y)), fmaxf(fabsf(v.z), fabsf(v.w)));
#pragma unroll
    for (int o = 16; o > 0; o >>= 1)
        amax = fmaxf(amax, __shfl_xor_sync(0xFFFFFFFFu, amax, o));
    const float s = fmaxf(amax, 1e-12f) / 448.0f;
    uchar4 q;
    q.x = fp8_q(v.x / s);
    q.y = fp8_q(v.y / s);
    q.z = fp8_q(v.z / s);
    q.w = fp8_q(v.w / s);
    *reinterpret_cast<uchar4*>(g_A + base) = q;
    if (lane == 0) g_SA[(size_t)m * NKB + kb] = s;
}

__global__ void __launch_bounds__(256) quant_w_kernel(const float* __restrict__ w) {
    const size_t e = ((size_t)blockIdx.x * 256 + threadIdx.x) * 4;
    const float4 v = *reinterpret_cast<const float4*>(w + e);
    uchar4 q;
    q.x = fp8_q(v.x);
    q.y = fp8_q(v.y);
    q.z = fp8_q(v.z);
    q.w = fp8_q(v.w);
    *reinterpret_cast<uchar4*>(g_W + e) = q;
}

// ------------------------------ GEMM kernel ------------------------------
// 128x128x64 CTA tile, 16 warps (4m x 4n), warp tile 32x32, fp8 mma m16n8k32.
// Two-level accumulation: exact q-products in temp, promoted to master with fp32
// block scales every 128-k block.
__global__ void __launch_bounds__(THREADS, 1) gemm_kernel(const float* __restrict__ wsi,
                                                          const float* __restrict__ bias,
                                                          float* __restrict__ out) {
    extern __shared__ __align__(128) char smem[];
    const uint32_t sb = smem_u32(smem);
    const int tid  = threadIdx.x;
    const int lane = tid & 31;
    const int wid  = tid >> 5;
    const int wm   = wid & 3;       // 4 warps along M
    const int wn   = wid >> 2;      // 4 warps along N
    const int m0 = blockIdx.y * BM;
    const int n0 = blockIdx.x * BN;
    const float* wsi_cta = wsi + blockIdx.x * NKB;   // s_w per k-block for this n-block

    float master[2][4][4];
    float temp[2][4][4];
#pragma unroll
    for (int i = 0; i < 2; ++i)
#pragma unroll
        for (int j = 0; j < 4; ++j)
#pragma unroll
            for (int q = 0; q < 4; ++q) { master[i][j][q] = 0.0f; temp[i][j][q] = 0.0f; }

    // producer: 1024 16B chunks per stage (A 512 + B 512), 2 per thread
    auto load_stage = [&](int k, int s) {
        const int k0 = k * BK;
        const uint32_t base = sb + s * STAGE_BYTES;
#pragma unroll
        for (int i = 0; i < 2; ++i) {
            const int cid  = tid + (i << 9);
            const int tile = cid >> 9;          // 0 = A, 1 = B
            const int w    = cid & 511;
            const int r    = w >> 2;
            const int ch   = w & 3;
            const uint8_t* src = (tile == 0)
                ? g_A + (size_t)(m0 + r) * KDIM + k0 + (ch << 4)
                : g_W + (size_t)(n0 + r) * KDIM + k0 + (ch << 4);
            const uint32_t dst = base + tile * TILE_BYTES
                + (uint32_t)(r * ROW_BYTES + (ch << 4));
            cp16(dst, src);
        }
    };

#pragma unroll
    for (int s = 0; s < STAGES - 1; ++s) { load_stage(s, s); cp_commit(); }

    const int arow0 = m0 + wm * 32 + (lane >> 2);    // this thread's scale rows

    for (int k = 0; k < KITERS; ++k) {
        cp_wait<STAGES - 2>();
        __syncthreads();

        const int s = k & (STAGES - 1);
        const uint32_t aBase = sb + s * STAGE_BYTES;
        const uint32_t bBase = aBase + TILE_BYTES;
#pragma unroll
        for (int kk = 0; kk < 2; ++kk) {           // two k32 steps per BK=64
            uint32_t a[2][4];
#pragma unroll
            for (int mi = 0; mi < 2; ++mi) {
                const int row = wm * 32 + mi * 16 + (lane & 15);
                ldsm_x4(a[mi], aBase + (uint32_t)(row * ROW_BYTES + kk * 32 + ((lane >> 4) << 4)));
            }
            uint32_t b[2][4];   // non-trans x4 on [n][k]: r0=(nlo,klo) r1=(nhi,klo) r2=(nlo,khi) r3=(nhi,khi)
#pragma unroll
            for (int nj = 0; nj < 2; ++nj) {
                const int row = wn * 32 + nj * 16 + (((lane >> 3) & 1) << 3) + (lane & 7);
                ldsm_x4(b[nj], bBase + (uint32_t)(row * ROW_BYTES + kk * 32 + ((lane >> 4) << 4)));
            }
#pragma unroll
            for (int mi = 0; mi < 2; ++mi)
#pragma unroll
                for (int ni = 0; ni < 4; ++ni)
                    mma_fp8(temp[mi][ni], a[mi], b[ni >> 1][ni & 1], b[ni >> 1][2 + (ni & 1)]);
        }

        const int kn = k + STAGES - 1;
        if (kn < KITERS) load_stage(kn, kn & (STAGES - 1));
        cp_commit();

        if (k & 1) {
            // promote: master += s_w(kb) * s_a(row,kb) * temp ; temp = 0
            const int kb = k >> 1;
            const float sw = __ldg(wsi_cta + kb);
            float comb[2][2];
#pragma unroll
            for (int mi = 0; mi < 2; ++mi)
#pragma unroll
                for (int h = 0; h < 2; ++h)
                    comb[mi][h] = sw * __ldg(g_SA + (size_t)(arow0 + mi * 16 + h * 8) * NKB + kb);
#pragma unroll
            for (int mi = 0; mi < 2; ++mi)
#pragma unroll
                for (int ni = 0; ni < 4; ++ni)
#pragma unroll
                    for (int q = 0; q < 4; ++q) {
                        master[mi][ni][q] = fmaf(comb[mi][q >> 1], temp[mi][ni][q], master[mi][ni][q]);
                        temp[mi][ni][q] = 0.0f;
                    }
        }
    }

    // -------- epilogue: bf16 arithmetic (match reference), write FLOAT32 --------
#pragma unroll
    for (int mi = 0; mi < 2; ++mi)
#pragma unroll
        for (int h = 0; h < 2; ++h) {
            const int grow = m0 + wm * 32 + mi * 16 + (lane >> 2) + h * 8;
            float* orow = out + (size_t)grow * NDIM;
#pragma unroll
            for (int ni = 0; ni < 4; ++ni) {
                const int col = n0 + wn * 32 + ni * 8 + ((lane & 3) << 1);
                const float b0 = __bfloat162float(__float2bfloat16(bias[col]));
                const float b1 = __bfloat162float(__float2bfloat16(bias[col + 1]));
                const float v0 = __bfloat162float(__float2bfloat16(master[mi][ni][h * 2 + 0]));
                const float v1 = __bfloat162float(__float2bfloat16(master[mi][ni][h * 2 + 1]));
                float2 o;
                o.x = __bfloat162float(__float2bfloat16(v0 + b0));
                o.y = __bfloat162float(__float2bfloat16(v1 + b1));
                *reinterpret_cast<float2*>(orow + col) = o;
            }
        }
}

// ------------------------------ launch ------------------------------
extern "C" void kernel_launch(void* const* d_in, const int* in_sizes, int n_in,
                              void* d_out, int out_size) {
    (void)out_size;
    // Bind inputs BY ELEMENT COUNT:
    //   x: 33554432, w: 16777216, wsi: 1024, bias: 4096
    const float* x    = nullptr;
    const float* w    = nullptr;
    const float* wsi  = nullptr;
    const float* bias = nullptr;
    for (int i = 0; i < n_in; ++i) {
        switch (in_sizes[i]) {
            case 33554432: x    = (const float*)d_in[i]; break;
            case 16777216: w    = (const float*)d_in[i]; break;
            case 1024:     wsi  = (const float*)d_in[i]; break;
            case 4096:     bias = (const float*)d_in[i]; break;
            default: break;
        }
    }
    float* out = (float*)d_out;     // __output__ is float32

    quant_x_kernel<<<MDIM * 4, 256>>>(x);
    quant_w_kernel<<<(NDIM * KDIM) / 1024, 256>>>(w);

    cudaFuncSetAttribute(gemm_kernel, cudaFuncAttributeMaxDynamicSharedMemorySize, SMEM_TOTAL);
    dim3 grid(NDIM / BN, MDIM / BM);                // (32, 64)
    gemm_kernel<<<grid, THREADS, SMEM_TOTAL>>>(wsi, bias, out);
}

// round 13
// speedup vs baseline: 1.0249x; 1.0024x over previous
#include <cuda_runtime.h>
#include <cuda_bf16.h>
#include <cuda_fp16.h>
#include <cuda_fp8.h>
#include <cstdint>
#include <cstddef>

#define MDIM 8192
#define KDIM 4096
#define NDIM 4096
#define BM 128
#define BN 128
#define BK 64
#define STAGES 4
#define KITERS (KDIM / BK)          // 64
#define NKB (KDIM / 128)            // 32 k-blocks
#define THREADS 512

// fp8 tile row: 64 B data + 16 B pad = 80 B stride.
// 8 consecutive rows -> byte offsets mod 128 = {0,80,32,112,64,16,96,48}: conflict-free ldmatrix.
#define ROW_BYTES 80
#define TILE_BYTES (128 * ROW_BYTES)          // 10240
#define STAGE_BYTES (2 * TILE_BYTES)          // A + B = 20480
#define SMEM_TOTAL (STAGES * STAGE_BYTES)     // 81920

// fused quant grid split
#define XBLOCKS (MDIM * 4)                    // 32768: warp per (row,128-block)
#define WBLOCKS ((NDIM * KDIM) / 1024)        // 16384: 4 elems/thread

// ---- scratch (static device arrays; no allocation) ----
__device__ uint8_t g_A[(size_t)MDIM * KDIM];   // raw e4m3 bytes of quantized x
__device__ uint8_t g_W[(size_t)NDIM * KDIM];   // raw e4m3 bytes of w
__device__ float   g_SA[(size_t)MDIM * NKB];   // activation scales [M][32]

// ------------------------------ PTX helpers ------------------------------
__device__ __forceinline__ uint32_t smem_u32(const void* p) {
    uint32_t a;
    asm("{ .reg .u64 t; cvta.to.shared.u64 t, %1; cvt.u32.u64 %0, t; }" : "=r"(a) : "l"(p));
    return a;
}
__device__ __forceinline__ void cp16(uint32_t dst, const void* src) {
    asm volatile("cp.async.cg.shared.global [%0], [%1], 16;" :: "r"(dst), "l"(src) : "memory");
}
__device__ __forceinline__ void cp_commit() {
    asm volatile("cp.async.commit_group;" ::: "memory");
}
template <int N>
__device__ __forceinline__ void cp_wait() {
    asm volatile("cp.async.wait_group %0;" :: "n"(N) : "memory");
}
__device__ __forceinline__ void ldsm_x4(uint32_t* r, uint32_t addr) {
    asm volatile("ldmatrix.sync.aligned.m8n8.x4.shared.b16 {%0,%1,%2,%3}, [%4];"
                 : "=r"(r[0]), "=r"(r[1]), "=r"(r[2]), "=r"(r[3]) : "r"(addr));
}
// fp8 e4m3 MMA, k32: same fragment wiring as f16 m16n8k16 with 2-fp8 "b16 units"
__device__ __forceinline__ void mma_fp8(float* c, const uint32_t* a, uint32_t b0, uint32_t b1) {
    asm volatile(
        "mma.sync.aligned.m16n8k32.row.col.f32.e4m3.e4m3.f32 "
        "{%0,%1,%2,%3}, {%4,%5,%6,%7}, {%8,%9}, {%0,%1,%2,%3};"
        : "+f"(c[0]), "+f"(c[1]), "+f"(c[2]), "+f"(c[3])
        : "r"(a[0]), "r"(a[1]), "r"(a[2]), "r"(a[3]), "r"(b0), "r"(b1));
}
// packed float2 -> e4m3x2 (RN, satfinite): low byte = lo, high byte = hi
__device__ __forceinline__ uint16_t cvt_e4m3x2(float hi, float lo) {
    uint16_t r;
    asm("cvt.rn.satfinite.e4m3x2.f32 %0, %1, %2;" : "=h"(r) : "f"(hi), "f"(lo));
    return r;
}
__device__ __forceinline__ uint32_t quant4(float v0, float v1, float v2, float v3) {
    return (uint32_t)cvt_e4m3x2(v1, v0) | ((uint32_t)cvt_e4m3x2(v3, v2) << 16);
}

// ------------------------------ fused quantize kernel ------------------------------
// Blocks [0, XBLOCKS): x path — one warp per (row, 128-block): amax -> scale -> e4m3
// Blocks [XBLOCKS, XBLOCKS+WBLOCKS): w path — elementwise e4m3
__global__ void __launch_bounds__(256) quant_fused_kernel(const float* __restrict__ x,
                                                          const float* __restrict__ w) {
    if (blockIdx.x < XBLOCKS) {
        const int gw   = (blockIdx.x * 256 + threadIdx.x) >> 5;
        const int lane = threadIdx.x & 31;
        const int m  = gw >> 5;
        const int kb = gw & 31;
        const size_t base = (size_t)m * KDIM + kb * 128 + lane * 4;
        const float4 v = *reinterpret_cast<const float4*>(x + base);
        float amax = fmaxf(fmaxf(fabsf(v.x), fabsf(v.y)), fmaxf(fabsf(v.z), fabsf(v.w)));
#pragma unroll
        for (int o = 16; o > 0; o >>= 1)
            amax = fmaxf(amax, __shfl_xor_sync(0xFFFFFFFFu, amax, o));
        const float s = fmaxf(amax, 1e-12f) / 448.0f;
        *reinterpret_cast<uint32_t*>(g_A + base) = quant4(v.x / s, v.y / s, v.z / s, v.w / s);
        if (lane == 0) g_SA[(size_t)m * NKB + kb] = s;
    } else {
        const size_t e = ((size_t)(blockIdx.x - XBLOCKS) * 256 + threadIdx.x) * 4;
        const float4 v = *reinterpret_cast<const float4*>(w + e);
        *reinterpret_cast<uint32_t*>(g_W + e) = quant4(v.x, v.y, v.z, v.w);
    }
}

// ------------------------------ GEMM kernel ------------------------------
// 128x128x64 CTA tile, 16 warps (4m x 4n), warp tile 32x32, fp8 mma m16n8k32.
// Two-level accumulation: exact q-products in temp, promoted to master with fp32
// block scales every 128-k block.
__global__ void __launch_bounds__(THREADS, 1) gemm_kernel(const float* __restrict__ wsi,
                                                          const float* __restrict__ bias,
                                                          float* __restrict__ out) {
    extern __shared__ __align__(128) char smem[];
    const uint32_t sb = smem_u32(smem);
    const int tid  = threadIdx.x;
    const int lane = tid & 31;
    const int wid  = tid >> 5;
    const int wm   = wid & 3;       // 4 warps along M
    const int wn   = wid >> 2;      // 4 warps along N
    const int m0 = blockIdx.y * BM;
    const int n0 = blockIdx.x * BN;
    const float* wsi_cta = wsi + blockIdx.x * NKB;   // s_w per k-block for this n-block

    float master[2][4][4];
    float temp[2][4][4];
#pragma unroll
    for (int i = 0; i < 2; ++i)
#pragma unroll
        for (int j = 0; j < 4; ++j)
#pragma unroll
            for (int q = 0; q < 4; ++q) { master[i][j][q] = 0.0f; temp[i][j][q] = 0.0f; }

    // producer: 1024 16B chunks per stage (A 512 + B 512), 2 per thread
    auto load_stage = [&](int k, int s) {
        const int k0 = k * BK;
        const uint32_t base = sb + s * STAGE_BYTES;
#pragma unroll
        for (int i = 0; i < 2; ++i) {
            const int cid  = tid + (i << 9);
            const int tile = cid >> 9;          // 0 = A, 1 = B
            const int w    = cid & 511;
            const int r    = w >> 2;
            const int ch   = w & 3;
            const uint8_t* src = (tile == 0)
                ? g_A + (size_t)(m0 + r) * KDIM + k0 + (ch << 4)
                : g_W + (size_t)(n0 + r) * KDIM + k0 + (ch << 4);
            const uint32_t dst = base + tile * TILE_BYTES
                + (uint32_t)(r * ROW_BYTES + (ch << 4));
            cp16(dst, src);
        }
    };

#pragma unroll
    for (int s = 0; s < STAGES - 1; ++s) { load_stage(s, s); cp_commit(); }

    const int arow0 = m0 + wm * 32 + (lane >> 2);    // this thread's scale rows

    for (int k = 0; k < KITERS; ++k) {
        cp_wait<STAGES - 2>();
        __syncthreads();

        const int s = k & (STAGES - 1);
        const uint32_t aBase = sb + s * STAGE_BYTES;
        const uint32_t bBase = aBase + TILE_BYTES;
#pragma unroll
        for (int kk = 0; kk < 2; ++kk) {           // two k32 steps per BK=64
            uint32_t a[2][4];
#pragma unroll
            for (int mi = 0; mi < 2; ++mi) {
                const int row = wm * 32 + mi * 16 + (lane & 15);
                ldsm_x4(a[mi], aBase + (uint32_t)(row * ROW_BYTES + kk * 32 + ((lane >> 4) << 4)));
            }
            uint32_t b[2][4];   // non-trans x4 on [n][k]: r0=(nlo,klo) r1=(nhi,klo) r2=(nlo,khi) r3=(nhi,khi)
#pragma unroll
            for (int nj = 0; nj < 2; ++nj) {
                const int row = wn * 32 + nj * 16 + (((lane >> 3) & 1) << 3) + (lane & 7);
                ldsm_x4(b[nj], bBase + (uint32_t)(row * ROW_BYTES + kk * 32 + ((lane >> 4) << 4)));
            }
#pragma unroll
            for (int mi = 0; mi < 2; ++mi)
#pragma unroll
                for (int ni = 0; ni < 4; ++ni)
                    mma_fp8(temp[mi][ni], a[mi], b[ni >> 1][ni & 1], b[ni >> 1][2 + (ni & 1)]);
        }

        const int kn = k + STAGES - 1;
        if (kn < KITERS) load_stage(kn, kn & (STAGES - 1));
        cp_commit();

        if (k & 1) {
            // promote: master += s_w(kb) * s_a(row,kb) * temp ; temp = 0
            const int kb = k >> 1;
            const float sw = __ldg(wsi_cta + kb);
            float comb[2][2];
#pragma unroll
            for (int mi = 0; mi < 2; ++mi)
#pragma unroll
                for (int h = 0; h < 2; ++h)
                    comb[mi][h] = sw * __ldg(g_SA + (size_t)(arow0 + mi * 16 + h * 8) * NKB + kb);
#pragma unroll
            for (int mi = 0; mi < 2; ++mi)
#pragma unroll
                for (int ni = 0; ni < 4; ++ni)
#pragma unroll
                    for (int q = 0; q < 4; ++q) {
                        master[mi][ni][q] = fmaf(comb[mi][q >> 1], temp[mi][ni][q], master[mi][ni][q]);
                        temp[mi][ni][q] = 0.0f;
                    }
        }
    }

    // -------- epilogue: bf16 arithmetic (match reference), write FLOAT32 --------
#pragma unroll
    for (int mi = 0; mi < 2; ++mi)
#pragma unroll
        for (int h = 0; h < 2; ++h) {
            const int grow = m0 + wm * 32 + mi * 16 + (lane >> 2) + h * 8;
            float* orow = out + (size_t)grow * NDIM;
#pragma unroll
            for (int ni = 0; ni < 4; ++ni) {
                const int col = n0 + wn * 32 + ni * 8 + ((lane & 3) << 1);
                const float b0 = __bfloat162float(__float2bfloat16(bias[col]));
                const float b1 = __bfloat162float(__float2bfloat16(bias[col + 1]));
                const float v0 = __bfloat162float(__float2bfloat16(master[mi][ni][h * 2 + 0]));
                const float v1 = __bfloat162float(__float2bfloat16(master[mi][ni][h * 2 + 1]));
                float2 o;
                o.x = __bfloat162float(__float2bfloat16(v0 + b0));
                o.y = __bfloat162float(__float2bfloat16(v1 + b1));
                *reinterpret_cast<float2*>(orow + col) = o;
            }
        }
}

// ------------------------------ launch ------------------------------
extern "C" void kernel_launch(void* const* d_in, const int* in_sizes, int n_in,
                              void* d_out, int out_size) {
    (void)out_size;
    // Bind inputs BY ELEMENT COUNT:
    //   x: 33554432, w: 16777216, wsi: 1024, bias: 4096
    const float* x    = nullptr;
    const float* w    = nullptr;
    const float* wsi  = nullptr;
    const float* bias = nullptr;
    for (int i = 0; i < n_in; ++i) {
        switch (in_sizes[i]) {
            case 33554432: x    = (const float*)d_in[i]; break;
            case 16777216: w    = (const float*)d_in[i]; break;
            case 1024:     wsi  = (const float*)d_in[i]; break;
            case 4096:     bias = (const float*)d_in[i]; break;
            default: break;
        }
    }
    float* out = (float*)d_out;     // __output__ is float32

    quant_fused_kernel<<<XBLOCKS + WBLOCKS, 256>>>(x, w);

    cudaFuncSetAttribute(gemm_kernel, cudaFuncAttributeMaxDynamicSharedMemorySize, SMEM_TOTAL);
    dim3 grid(NDIM / BN, MDIM / BM);                // (32, 64)
    gemm_kernel<<<grid, THREADS, SMEM_TOTAL>>>(wsi, bias, out);
}

// round 14
// speedup vs baseline: 1.0998x; 1.0731x over previous
#include <cuda_runtime.h>
#include <cuda_bf16.h>
#include <cuda_fp16.h>
#include <cuda_fp8.h>
#include <cstdint>
#include <cstddef>

#define MDIM 8192
#define KDIM 4096
#define NDIM 4096
#define BM 128
#define BN 128
#define BK 128
#define STAGES 3
#define KITERS (KDIM / BK)          // 32
#define NKB (KDIM / 128)            // 32 k-blocks
#define THREADS 256

// fp8 tile row: 128 B data + 16 B pad = 144 B stride.
// 8 consecutive rows -> offsets mod 128 = {0,16,32,48,64,80,96,112}: conflict-free ldmatrix.
#define ROW_BYTES 144
#define TILE_BYTES (128 * ROW_BYTES)          // 18432
#define STAGE_BYTES (2 * TILE_BYTES)          // A + B = 36864
#define SMEM_TOTAL (STAGES * STAGE_BYTES)     // 110592

// fused quant grid split
#define XBLOCKS (MDIM * 4)                    // 32768: warp per (row,128-block)
#define WBLOCKS ((NDIM * KDIM) / 1024)        // 16384: 4 elems/thread

// ---- scratch (static device arrays; no allocation) ----
__device__ uint8_t g_A[(size_t)MDIM * KDIM];   // raw e4m3 bytes of quantized x
__device__ uint8_t g_W[(size_t)NDIM * KDIM];   // raw e4m3 bytes of w
__device__ float   g_SA[(size_t)MDIM * NKB];   // activation scales [M][32]

// ------------------------------ PTX helpers ------------------------------
__device__ __forceinline__ uint32_t smem_u32(const void* p) {
    uint32_t a;
    asm("{ .reg .u64 t; cvta.to.shared.u64 t, %1; cvt.u32.u64 %0, t; }" : "=r"(a) : "l"(p));
    return a;
}
__device__ __forceinline__ void cp16(uint32_t dst, const void* src) {
    asm volatile("cp.async.cg.shared.global [%0], [%1], 16;" :: "r"(dst), "l"(src) : "memory");
}
__device__ __forceinline__ void cp_commit() {
    asm volatile("cp.async.commit_group;" ::: "memory");
}
template <int N>
__device__ __forceinline__ void cp_wait() {
    asm volatile("cp.async.wait_group %0;" :: "n"(N) : "memory");
}
__device__ __forceinline__ void ldsm_x4(uint32_t* r, uint32_t addr) {
    asm volatile("ldmatrix.sync.aligned.m8n8.x4.shared.b16 {%0,%1,%2,%3}, [%4];"
                 : "=r"(r[0]), "=r"(r[1]), "=r"(r[2]), "=r"(r[3]) : "r"(addr));
}
// fp8 e4m3 MMA, k32: same fragment wiring as f16 m16n8k16 with 2-fp8 "b16 units"
__device__ __forceinline__ void mma_fp8(float* c, const uint32_t* a, uint32_t b0, uint32_t b1) {
    asm volatile(
        "mma.sync.aligned.m16n8k32.row.col.f32.e4m3.e4m3.f32 "
        "{%0,%1,%2,%3}, {%4,%5,%6,%7}, {%8,%9}, {%0,%1,%2,%3};"
        : "+f"(c[0]), "+f"(c[1]), "+f"(c[2]), "+f"(c[3])
        : "r"(a[0]), "r"(a[1]), "r"(a[2]), "r"(a[3]), "r"(b0), "r"(b1));
}
// packed float2 -> e4m3x2 (RN, satfinite): low byte = lo, high byte = hi
__device__ __forceinline__ uint16_t cvt_e4m3x2(float hi, float lo) {
    uint16_t r;
    asm("cvt.rn.satfinite.e4m3x2.f32 %0, %1, %2;" : "=h"(r) : "f"(hi), "f"(lo));
    return r;
}
__device__ __forceinline__ uint32_t quant4(float v0, float v1, float v2, float v3) {
    return (uint32_t)cvt_e4m3x2(v1, v0) | ((uint32_t)cvt_e4m3x2(v3, v2) << 16);
}

// ------------------------------ fused quantize kernel ------------------------------
__global__ void __launch_bounds__(256) quant_fused_kernel(const float* __restrict__ x,
                                                          const float* __restrict__ w) {
    if (blockIdx.x < XBLOCKS) {
        const int gw   = (blockIdx.x * 256 + threadIdx.x) >> 5;
        const int lane = threadIdx.x & 31;
        const int m  = gw >> 5;
        const int kb = gw & 31;
        const size_t base = (size_t)m * KDIM + kb * 128 + lane * 4;
        const float4 v = *reinterpret_cast<const float4*>(x + base);
        float amax = fmaxf(fmaxf(fabsf(v.x), fabsf(v.y)), fmaxf(fabsf(v.z), fabsf(v.w)));
#pragma unroll
        for (int o = 16; o > 0; o >>= 1)
            amax = fmaxf(amax, __shfl_xor_sync(0xFFFFFFFFu, amax, o));
        const float s = fmaxf(amax, 1e-12f) / 448.0f;
        *reinterpret_cast<uint32_t*>(g_A + base) = quant4(v.x / s, v.y / s, v.z / s, v.w / s);
        if (lane == 0) g_SA[(size_t)m * NKB + kb] = s;
    } else {
        const size_t e = ((size_t)(blockIdx.x - XBLOCKS) * 256 + threadIdx.x) * 4;
        const float4 v = *reinterpret_cast<const float4*>(w + e);
        *reinterpret_cast<uint32_t*>(g_W + e) = quant4(v.x, v.y, v.z, v.w);
    }
}

// ------------------------------ GEMM kernel ------------------------------
// 128x128x128 CTA tile, 8 warps (2m x 4n), warp tile 64x32, fp8 mma m16n8k32.
// Promote temp -> master with fp32 block scales once per iteration (BK = 128 = scale block).
__global__ void __launch_bounds__(THREADS, 1) gemm_kernel(const float* __restrict__ wsi,
                                                          const float* __restrict__ bias,
                                                          float* __restrict__ out) {
    extern __shared__ __align__(128) char smem[];
    const uint32_t sb = smem_u32(smem);
    const int tid  = threadIdx.x;
    const int lane = tid & 31;
    const int wid  = tid >> 5;
    const int wm   = wid & 1;       // 2 warps along M (64 rows each)
    const int wn   = wid >> 1;      // 4 warps along N (32 cols each)
    const int m0 = blockIdx.y * BM;
    const int n0 = blockIdx.x * BN;
    const float* wsi_cta = wsi + blockIdx.x * NKB;   // s_w per k-block for this n-block

    float master[4][4][4];
    float temp[4][4][4];
#pragma unroll
    for (int i = 0; i < 4; ++i)
#pragma unroll
        for (int j = 0; j < 4; ++j)
#pragma unroll
            for (int q = 0; q < 4; ++q) { master[i][j][q] = 0.0f; temp[i][j][q] = 0.0f; }

    // producer: 2048 16B chunks per stage (A 1024 + B 1024), 8 per thread.
    // Per-thread source pointers advance by BK per stage; dst offsets fixed.
    const uint8_t* srcs[8];
    uint32_t doff[8];
#pragma unroll
    for (int i = 0; i < 8; ++i) {
        const int cid  = tid + (i << 8);
        const int tile = cid >> 10;         // 0 = A, 1 = B
        const int w    = cid & 1023;
        const int r    = w >> 3;
        const int ch   = w & 7;
        srcs[i] = (tile == 0 ? g_A + (size_t)(m0 + r) * KDIM
                             : g_W + (size_t)(n0 + r) * KDIM) + (ch << 4);
        doff[i] = (uint32_t)(tile * TILE_BYTES + r * ROW_BYTES + (ch << 4));
    }
    auto load_stage = [&](int s) {
        const uint32_t base = sb + s * STAGE_BYTES;
#pragma unroll
        for (int i = 0; i < 8; ++i) {
            cp16(base + doff[i], srcs[i]);
            srcs[i] += BK;
        }
    };

    load_stage(0); cp_commit();
    load_stage(1); cp_commit();

    const int arow0 = m0 + wm * 64 + (lane >> 2);    // this thread's scale-row base

    for (int k = 0; k < KITERS; ++k) {
        cp_wait<1>();
        __syncthreads();

        const int s = k - (k / STAGES) * STAGES;     // k % 3
        const uint32_t aBase = sb + s * STAGE_BYTES;
        const uint32_t bBase = aBase + TILE_BYTES;
#pragma unroll
        for (int kk = 0; kk < 4; ++kk) {             // four k32 steps per BK=128
            const uint32_t coff = (uint32_t)(kk * 32 + ((lane >> 4) << 4));
            uint32_t a[4][4];
#pragma unroll
            for (int mi = 0; mi < 4; ++mi) {
                const int row = wm * 64 + mi * 16 + (lane & 15);
                ldsm_x4(a[mi], aBase + (uint32_t)(row * ROW_BYTES) + coff);
            }
            uint32_t b[2][4];   // non-trans x4 on [n][k]: r0=(nlo,klo) r1=(nhi,klo) r2=(nlo,khi) r3=(nhi,khi)
#pragma unroll
            for (int nj = 0; nj < 2; ++nj) {
                const int row = wn * 32 + nj * 16 + (((lane >> 3) & 1) << 3) + (lane & 7);
                ldsm_x4(b[nj], bBase + (uint32_t)(row * ROW_BYTES) + coff);
            }
#pragma unroll
            for (int mi = 0; mi < 4; ++mi)
#pragma unroll
                for (int ni = 0; ni < 4; ++ni)
                    mma_fp8(temp[mi][ni], a[mi], b[ni >> 1][ni & 1], b[ni >> 1][2 + (ni & 1)]);
        }

        if (k + 2 < KITERS) load_stage((k + 2) - ((k + 2) / STAGES) * STAGES);
        cp_commit();

        // promote: master += s_w(k) * s_a(row,k) * temp ; temp = 0   (BK == scale block)
        const float sw = __ldg(wsi_cta + k);
        float comb[4][2];
#pragma unroll
        for (int mi = 0; mi < 4; ++mi)
#pragma unroll
            for (int h = 0; h < 2; ++h)
                comb[mi][h] = sw * __ldg(g_SA + (size_t)(arow0 + mi * 16 + h * 8) * NKB + k);
#pragma unroll
        for (int mi = 0; mi < 4; ++mi)
#pragma unroll
            for (int ni = 0; ni < 4; ++ni)
#pragma unroll
                for (int q = 0; q < 4; ++q) {
                    master[mi][ni][q] = fmaf(comb[mi][q >> 1], temp[mi][ni][q], master[mi][ni][q]);
                    temp[mi][ni][q] = 0.0f;
                }
    }

    // -------- epilogue: bf16 arithmetic (match reference), write FLOAT32 --------
#pragma unroll
    for (int mi = 0; mi < 4; ++mi)
#pragma unroll
        for (int h = 0; h < 2; ++h) {
            const int grow = m0 + wm * 64 + mi * 16 + (lane >> 2) + h * 8;
            float* orow = out + (size_t)grow * NDIM;
#pragma unroll
            for (int ni = 0; ni < 4; ++ni) {
                const int col = n0 + wn * 32 + ni * 8 + ((lane & 3) << 1);
                const float b0 = __bfloat162float(__float2bfloat16(bias[col]));
                const float b1 = __bfloat162float(__float2bfloat16(bias[col + 1]));
                const float v0 = __bfloat162float(__float2bfloat16(master[mi][ni][h * 2 + 0]));
                const float v1 = __bfloat162float(__float2bfloat16(master[mi][ni][h * 2 + 1]));
                float2 o;
                o.x = __bfloat162float(__float2bfloat16(v0 + b0));
                o.y = __bfloat162float(__float2bfloat16(v1 + b1));
                *reinterpret_cast<float2*>(orow + col) = o;
            }
        }
}

// ------------------------------ launch ------------------------------
extern "C" void kernel_launch(void* const* d_in, const int* in_sizes, int n_in,
                              void* d_out, int out_size) {
    (void)out_size;
    // Bind inputs BY ELEMENT COUNT:
    //   x: 33554432, w: 16777216, wsi: 1024, bias: 4096
    const float* x    = nullptr;
    const float* w    = nullptr;
    const float* wsi  = nullptr;
    const float* bias = nullptr;
    for (int i = 0; i < n_in; ++i) {
        switch (in_sizes[i]) {
            case 33554432: x    = (const float*)d_in[i]; break;
            case 16777216: w    = (const float*)d_in[i]; break;
            case 1024:     wsi  = (const float*)d_in[i]; break;
            case 4096:     bias = (const float*)d_in[i]; break;
            default: break;
        }
    }
    float* out = (float*)d_out;     // __output__ is float32

    quant_fused_kernel<<<XBLOCKS + WBLOCKS, 256>>>(x, w);

    cudaFuncSetAttribute(gemm_kernel, cudaFuncAttributeMaxDynamicSharedMemorySize, SMEM_TOTAL);
    dim3 grid(NDIM / BN, MDIM / BM);                // (32, 64)
    gemm_kernel<<<grid, THREADS, SMEM_TOTAL>>>(wsi, bias, out);
}

// round 16
// speedup vs baseline: 1.1126x; 1.0117x over previous
#include <cuda_runtime.h>
#include <cuda_bf16.h>
#include <cuda_fp16.h>
#include <cuda_fp8.h>
#include <cstdint>
#include <cstddef>

#define MDIM 8192
#define KDIM 4096
#define NDIM 4096
#define BM 128
#define BN 128
#define BK 128
#define STAGES 3
#define KITERS (KDIM / BK)          // 32
#define NKB (KDIM / 128)            // 32 k-blocks
#define THREADS 512

// fp8 tile row: 128 B data + 16 B pad = 144 B stride (conflict-free ldmatrix).
#define ROW_BYTES 144
#define TILE_BYTES (128 * ROW_BYTES)          // 18432
#define STAGE_BYTES (2 * TILE_BYTES)          // A + B = 36864
#define SMEM_TOTAL (STAGES * STAGE_BYTES)     // 110592

// fused quant grid split
#define XBLOCKS (MDIM * 4)                    // 32768: warp per (row,128-block)
#define WBLOCKS ((NDIM * KDIM) / 1024)        // 16384: 4 elems/thread

// ---- scratch (static device arrays; no allocation) ----
__device__ uint8_t g_A[(size_t)MDIM * KDIM];   // raw e4m3 bytes of quantized x
__device__ uint8_t g_W[(size_t)NDIM * KDIM];   // raw e4m3 bytes of w
__device__ float   g_SA[(size_t)MDIM * NKB];   // activation scales [M][32]

// ------------------------------ PTX helpers ------------------------------
__device__ __forceinline__ uint32_t smem_u32(const void* p) {
    uint32_t a;
    asm("{ .reg .u64 t; cvta.to.shared.u64 t, %1; cvt.u32.u64 %0, t; }" : "=r"(a) : "l"(p));
    return a;
}
__device__ __forceinline__ void cp16(uint32_t dst, const void* src) {
    asm volatile("cp.async.cg.shared.global [%0], [%1], 16;" :: "r"(dst), "l"(src) : "memory");
}
__device__ __forceinline__ void cp_commit() {
    asm volatile("cp.async.commit_group;" ::: "memory");
}
template <int N>
__device__ __forceinline__ void cp_wait() {
    asm volatile("cp.async.wait_group %0;" :: "n"(N) : "memory");
}
__device__ __forceinline__ void ldsm_x4(uint32_t* r, uint32_t addr) {
    asm volatile("ldmatrix.sync.aligned.m8n8.x4.shared.b16 {%0,%1,%2,%3}, [%4];"
                 : "=r"(r[0]), "=r"(r[1]), "=r"(r[2]), "=r"(r[3]) : "r"(addr));
}
// fp8 e4m3 MMA k32, accumulate into c
__device__ __forceinline__ void mma_fp8(float* c, const uint32_t* a, uint32_t b0, uint32_t b1) {
    asm volatile(
        "mma.sync.aligned.m16n8k32.row.col.f32.e4m3.e4m3.f32 "
        "{%0,%1,%2,%3}, {%4,%5,%6,%7}, {%8,%9}, {%0,%1,%2,%3};"
        : "+f"(c[0]), "+f"(c[1]), "+f"(c[2]), "+f"(c[3])
        : "r"(a[0]), "r"(a[1]), "r"(a[2]), "r"(a[3]), "r"(b0), "r"(b1));
}
// fp8 e4m3 MMA k32, zero accumulator input: c = a*b (no temp re-zeroing needed)
__device__ __forceinline__ void mma_fp8_zc(float* c, const uint32_t* a, uint32_t b0, uint32_t b1,
                                           float z) {
    asm volatile(
        "mma.sync.aligned.m16n8k32.row.col.f32.e4m3.e4m3.f32 "
        "{%0,%1,%2,%3}, {%4,%5,%6,%7}, {%8,%9}, {%10,%10,%10,%10};"
        : "=f"(c[0]), "=f"(c[1]), "=f"(c[2]), "=f"(c[3])
        : "r"(a[0]), "r"(a[1]), "r"(a[2]), "r"(a[3]), "r"(b0), "r"(b1), "f"(z));
}
// packed float2 -> e4m3x2 (RN, satfinite)
__device__ __forceinline__ uint16_t cvt_e4m3x2(float hi, float lo) {
    uint16_t r;
    asm("cvt.rn.satfinite.e4m3x2.f32 %0, %1, %2;" : "=h"(r) : "f"(hi), "f"(lo));
    return r;
}
__device__ __forceinline__ uint32_t quant4(float v0, float v1, float v2, float v3) {
    return (uint32_t)cvt_e4m3x2(v1, v0) | ((uint32_t)cvt_e4m3x2(v3, v2) << 16);
}

// ------------------------------ fused quantize kernel ------------------------------
__global__ void __launch_bounds__(256) quant_fused_kernel(const float* __restrict__ x,
                                                          const float* __restrict__ w) {
    if (blockIdx.x < XBLOCKS) {
        const int gw   = (blockIdx.x * 256 + threadIdx.x) >> 5;
        const int lane = threadIdx.x & 31;
        const int m  = gw >> 5;
        const int kb = gw & 31;
        const size_t base = (size_t)m * KDIM + kb * 128 + lane * 4;
        const float4 v = *reinterpret_cast<const float4*>(x + base);
        float amax = fmaxf(fmaxf(fabsf(v.x), fabsf(v.y)), fmaxf(fabsf(v.z), fabsf(v.w)));
#pragma unroll
        for (int o = 16; o > 0; o >>= 1)
            amax = fmaxf(amax, __shfl_xor_sync(0xFFFFFFFFu, amax, o));
        const float s = fmaxf(amax, 1e-12f) / 448.0f;
        *reinterpret_cast<uint32_t*>(g_A + base) = quant4(v.x / s, v.y / s, v.z / s, v.w / s);
        if (lane == 0) g_SA[(size_t)m * NKB + kb] = s;
    } else {
        const size_t e = ((size_t)(blockIdx.x - XBLOCKS) * 256 + threadIdx.x) * 4;
        const float4 v = *reinterpret_cast<const float4*>(w + e);
        *reinterpret_cast<uint32_t*>(g_W + e) = quant4(v.x, v.y, v.z, v.w);
    }
}

// ------------------------------ GEMM kernel ------------------------------
// 128x128x128 CTA tile, 16 warps (4m x 4n), warp tile 32x32, fp8 mma m16n8k32.
// temp = fresh per k-block via zero-acc first mma; promoted to master with fp32
// block scales once per iteration (BK = 128 = scale block).
__global__ void __launch_bounds__(THREADS, 1) gemm_kernel(const float* __restrict__ wsi,
                                                          const float* __restrict__ bias,
                                                          float* __restrict__ out) {
    extern __shared__ __align__(128) char smem[];
    const uint32_t sb = smem_u32(smem);
    const int tid  = threadIdx.x;
    const int lane = tid & 31;
    const int wid  = tid >> 5;
    const int wm   = wid & 3;       // 4 warps along M (32 rows each)
    const int wn   = wid >> 2;      // 4 warps along N (32 cols each)
    const int m0 = blockIdx.y * BM;
    const int n0 = blockIdx.x * BN;
    const float* wsi_cta = wsi + blockIdx.x * NKB;

    float master[2][4][4];
    float temp[2][4][4];
#pragma unroll
    for (int i = 0; i < 2; ++i)
#pragma unroll
        for (int j = 0; j < 4; ++j)
#pragma unroll
            for (int q = 0; q < 4; ++q) master[i][j][q] = 0.0f;

    // producer: 2048 16B chunks per stage (A 1024 + B 1024), 4 per thread.
    const uint8_t* srcs[4];
    uint32_t doff[4];
#pragma unroll
    for (int i = 0; i < 4; ++i) {
        const int cid  = tid + (i << 9);
        const int tile = cid >> 10;         // 0 = A, 1 = B
        const int w    = cid & 1023;
        const int r    = w >> 3;
        const int ch   = w & 7;
        srcs[i] = (tile == 0 ? g_A + (size_t)(m0 + r) * KDIM
                             : g_W + (size_t)(n0 + r) * KDIM) + (ch << 4);
        doff[i] = (uint32_t)(tile * TILE_BYTES + r * ROW_BYTES + (ch << 4));
    }
    auto load_stage = [&](int s) {
        const uint32_t base = sb + s * STAGE_BYTES;
#pragma unroll
        for (int i = 0; i < 4; ++i) {
            cp16(base + doff[i], srcs[i]);
            srcs[i] += BK;
        }
    };

    load_stage(0); cp_commit();
    load_stage(1); cp_commit();

    const int arow0 = m0 + wm * 32 + (lane >> 2);    // this thread's scale-row base
    const float zf = 0.0f;
    int s_cur = 0, s_nxt = 2;

    for (int k = 0; k < KITERS; ++k) {
        cp_wait<1>();
        __syncthreads();

        // prefetch this block's scales early; latency hides under the mma loop
        const float sw = __ldg(wsi_cta + k);
        float sa[2][2];
#pragma unroll
        for (int mi = 0; mi < 2; ++mi)
#pragma unroll
            for (int h = 0; h < 2; ++h)
                sa[mi][h] = __ldg(g_SA + (size_t)(arow0 + mi * 16 + h * 8) * NKB + k);

        const uint32_t aBase = sb + s_cur * STAGE_BYTES;
        const uint32_t bBase = aBase + TILE_BYTES;
#pragma unroll
        for (int kk = 0; kk < 4; ++kk) {             // four k32 steps per BK=128
            const uint32_t coff = (uint32_t)(kk * 32 + ((lane >> 4) << 4));
            uint32_t a[2][4];
#pragma unroll
            for (int mi = 0; mi < 2; ++mi) {
                const int row = wm * 32 + mi * 16 + (lane & 15);
                ldsm_x4(a[mi], aBase + (uint32_t)(row * ROW_BYTES) + coff);
            }
            uint32_t b[2][4];   // non-trans x4 on [n][k]: r0=(nlo,klo) r1=(nhi,klo) r2=(nlo,khi) r3=(nhi,khi)
#pragma unroll
            for (int nj = 0; nj < 2; ++nj) {
                const int row = wn * 32 + nj * 16 + (((lane >> 3) & 1) << 3) + (lane & 7);
                ldsm_x4(b[nj], bBase + (uint32_t)(row * ROW_BYTES) + coff);
            }
            if (kk == 0) {
#pragma unroll
                for (int mi = 0; mi < 2; ++mi)
#pragma unroll
                    for (int ni = 0; ni < 4; ++ni)
                        mma_fp8_zc(temp[mi][ni], a[mi], b[ni >> 1][ni & 1], b[ni >> 1][2 + (ni & 1)], zf);
            } else {
#pragma unroll
                for (int mi = 0; mi < 2; ++mi)
#pragma unroll
                    for (int ni = 0; ni < 4; ++ni)
                        mma_fp8(temp[mi][ni], a[mi], b[ni >> 1][ni & 1], b[ni >> 1][2 + (ni & 1)]);
            }
        }

        if (k + 2 < KITERS) load_stage(s_nxt);
        cp_commit();
        if (++s_cur == STAGES) s_cur = 0;
        if (++s_nxt == STAGES) s_nxt = 0;

        // promote: master += sw * sa(row) * temp   (no temp reset needed)
#pragma unroll
        for (int mi = 0; mi < 2; ++mi) {
            const float c0 = sw * sa[mi][0];
            const float c1 = sw * sa[mi][1];
#pragma unroll
            for (int ni = 0; ni < 4; ++ni) {
                master[mi][ni][0] = fmaf(c0, temp[mi][ni][0], master[mi][ni][0]);
                master[mi][ni][1] = fmaf(c0, temp[mi][ni][1], master[mi][ni][1]);
                master[mi][ni][2] = fmaf(c1, temp[mi][ni][2], master[mi][ni][2]);
                master[mi][ni][3] = fmaf(c1, temp[mi][ni][3], master[mi][ni][3]);
            }
        }
    }

    // -------- epilogue: bf16 arithmetic (match reference), write FLOAT32 --------
#pragma unroll
    for (int mi = 0; mi < 2; ++mi)
#pragma unroll
        for (int h = 0; h < 2; ++h) {
            const int grow = m0 + wm * 32 + mi * 16 + (lane >> 2) + h * 8;
            float* orow = out + (size_t)grow * NDIM;
#pragma unroll
            for (int ni = 0; ni < 4; ++ni) {
                const int col = n0 + wn * 32 + ni * 8 + ((lane & 3) << 1);
                const float b0 = __bfloat162float(__float2bfloat16(bias[col]));
                const float b1 = __bfloat162float(__float2bfloat16(bias[col + 1]));
                const float v0 = __bfloat162float(__float2bfloat16(master[mi][ni][h * 2 + 0]));
                const float v1 = __bfloat162float(__float2bfloat16(master[mi][ni][h * 2 + 1]));
                float2 o;
                o.x = __bfloat162float(__float2bfloat16(v0 + b0));
                o.y = __bfloat162float(__float2bfloat16(v1 + b1));
                *reinterpret_cast<float2*>(orow + col) = o;
            }
        }
}

// ------------------------------ launch ------------------------------
extern "C" void kernel_launch(void* const* d_in, const int* in_sizes, int n_in,
                              void* d_out, int out_size) {
    (void)out_size;
    // Bind inputs BY ELEMENT COUNT:
    //   x: 33554432, w: 16777216, wsi: 1024, bias: 4096
    const float* x    = nullptr;
    const float* w    = nullptr;
    const float* wsi  = nullptr;
    const float* bias = nullptr;
    for (int i = 0; i < n_in; ++i) {
        switch (in_sizes[i]) {
            case 33554432: x    = (const float*)d_in[i]; break;
            case 16777216: w    = (const float*)d_in[i]; break;
            case 1024:     wsi  = (const float*)d_in[i]; break;
            case 4096:     bias = (const float*)d_in[i]; break;
            default: break;
        }
    }
    float* out = (float*)d_out;     // __output__ is float32

    quant_fused_kernel<<<XBLOCKS + WBLOCKS, 256>>>(x, w);

    cudaFuncSetAttribute(gemm_kernel, cudaFuncAttributeMaxDynamicSharedMemorySize, SMEM_TOTAL);
    dim3 grid(NDIM / BN, MDIM / BM);                // (32, 64)
    gemm_kernel<<<grid, THREADS, SMEM_TOTAL>>>(wsi, bias, out);
}